// round 1
// baseline (speedup 1.0000x reference)
#include <cuda_runtime.h>
#include <math.h>

// ---------------------------------------------------------------------------
// MHSA: x[16,1024,768] -> qkv gemm -> attention (12 heads, d=64) -> proj gemm
// fp32 throughout. Scratch in __device__ globals (no allocation).
// ---------------------------------------------------------------------------

#define BATCH   16
#define SEQ     1024
#define DIM     768
#define HEADS   12
#define HD      64
#define MTOT    (BATCH * SEQ)      // 16384
#define QKVN    (3 * DIM)          // 2304
#define NBH     (BATCH * HEADS)    // 192

// Scratch: Q,K stored d-major per head: [bh][d][n]; V natural: [bh][n][d]
__device__ float g_q[(size_t)NBH * HD * SEQ];
__device__ float g_k[(size_t)NBH * HD * SEQ];
__device__ float g_v[(size_t)NBH * SEQ * HD];
__device__ float g_att[(size_t)MTOT * DIM];   // [b*N+n][h*64+d]

// ---------------------------------------------------------------------------
// GEMM 1: qkv = x @ w_qkv + b_qkv, scattered into g_q/g_k/g_v
// 128x128x16 tiles, 256 threads, 8x8 per thread.
// ---------------------------------------------------------------------------
__global__ __launch_bounds__(256, 2)
void qkv_gemm_kernel(const float* __restrict__ X,
                     const float* __restrict__ W,
                     const float* __restrict__ bias) {
    __shared__ float As[16][132];
    __shared__ float Bs[16][132];

    const int K = DIM;        // 768
    const int NN = QKVN;      // 2304

    const int bn = blockIdx.x;           // 0..17
    const int bm = blockIdx.y;           // 0..127
    const int tid = threadIdx.x;
    const int tx = tid & 15;
    const int ty = tid >> 4;
    const int gm0 = bm * 128;
    const int gn0 = bn * 128;

    float acc[8][8];
    #pragma unroll
    for (int i = 0; i < 8; i++)
        #pragma unroll
        for (int j = 0; j < 8; j++) acc[i][j] = 0.f;

    for (int kt = 0; kt < K / 16; ++kt) {
        #pragma unroll
        for (int i = 0; i < 2; ++i) {
            int l = tid + i * 256;
            int ar = l >> 2, ac = (l & 3) << 2;
            float4 va = *(const float4*)(X + (size_t)(gm0 + ar) * K + kt * 16 + ac);
            As[ac + 0][ar] = va.x;
            As[ac + 1][ar] = va.y;
            As[ac + 2][ar] = va.z;
            As[ac + 3][ar] = va.w;
            int br = l >> 5, bc = (l & 31) << 2;
            float4 vb = *(const float4*)(W + (size_t)(kt * 16 + br) * NN + gn0 + bc);
            *(float4*)&Bs[br][bc] = vb;
        }
        __syncthreads();
        #pragma unroll
        for (int kk = 0; kk < 16; ++kk) {
            float af[8], bf[8];
            *(float4*)(af + 0) = *(const float4*)&As[kk][ty * 8 + 0];
            *(float4*)(af + 4) = *(const float4*)&As[kk][ty * 8 + 4];
            *(float4*)(bf + 0) = *(const float4*)&Bs[kk][tx * 8 + 0];
            *(float4*)(bf + 4) = *(const float4*)&Bs[kk][tx * 8 + 4];
            #pragma unroll
            for (int i = 0; i < 8; i++)
                #pragma unroll
                for (int j = 0; j < 8; j++) acc[i][j] += af[i] * bf[j];
        }
        __syncthreads();
    }

    // epilogue: col c -> (s, h, dd); row m -> (b, n)
    const int c0 = gn0 + tx * 8;
    const int s  = c0 / 768;
    const int rm = c0 % 768;
    const int h  = rm >> 6;
    const int dd0 = rm & 63;
    const int m0 = gm0 + ty * 8;
    const int bb = m0 >> 10;
    const int n0 = m0 & 1023;
    const int bh = bb * HEADS + h;

    float bv[8];
    #pragma unroll
    for (int j = 0; j < 8; j++) bv[j] = bias[c0 + j];

    if (s == 2) {
        // V natural: [bh][n][dd]
        #pragma unroll
        for (int i = 0; i < 8; i++) {
            float* dst = g_v + ((size_t)bh * SEQ + (n0 + i)) * HD + dd0;
            float4 lo = make_float4(acc[i][0] + bv[0], acc[i][1] + bv[1],
                                    acc[i][2] + bv[2], acc[i][3] + bv[3]);
            float4 hi = make_float4(acc[i][4] + bv[4], acc[i][5] + bv[5],
                                    acc[i][6] + bv[6], acc[i][7] + bv[7]);
            *(float4*)(dst + 0) = lo;
            *(float4*)(dst + 4) = hi;
        }
    } else {
        // Q/K d-major: [bh][dd][n]
        float* base = (s == 0 ? g_q : g_k) + (size_t)bh * HD * SEQ;
        #pragma unroll
        for (int j = 0; j < 8; j++) {
            float* dst = base + (size_t)(dd0 + j) * SEQ + n0;
            float4 lo = make_float4(acc[0][j] + bv[j], acc[1][j] + bv[j],
                                    acc[2][j] + bv[j], acc[3][j] + bv[j]);
            float4 hi = make_float4(acc[4][j] + bv[j], acc[5][j] + bv[j],
                                    acc[6][j] + bv[j], acc[7][j] + bv[j]);
            *(float4*)(dst + 0) = lo;
            *(float4*)(dst + 4) = hi;
        }
    }
}

// ---------------------------------------------------------------------------
// Attention: per CTA: one (bh, q-tile of 32 rows). Full 1024-key score row in
// SMEM, exact softmax, then P@V. 256 threads.
// ---------------------------------------------------------------------------
#define SS_STRIDE 1032           // floats; (1032 % 32)==8 -> conflict-free softmax scan
#define KS_STRIDE 132
#define QS_STRIDE 36
#define VS_STRIDE 68

#define ATTN_SMEM_FLOATS (32 * SS_STRIDE + 64 * KS_STRIDE + 64 * QS_STRIDE)
#define ATTN_SMEM_BYTES  (ATTN_SMEM_FLOATS * 4)

#define P_COMP(p, jj) ((jj) == 0 ? (p).x : (jj) == 1 ? (p).y : (jj) == 2 ? (p).z : (p).w)

__global__ __launch_bounds__(256)
void attn_kernel() {
    extern __shared__ float sm[];
    float* Ss = sm;                                  // [32][SS_STRIDE]
    float* Ks = sm + 32 * SS_STRIDE;                 // [64][KS_STRIDE]
    float* Qs = Ks + 64 * KS_STRIDE;                 // [64][QS_STRIDE]
    float* Vs = Ks;                                  // alias over Ks+Qs: [128][VS_STRIDE]
    __shared__ float rowsum[32];

    const int blk = blockIdx.x;
    const int bh = blk >> 5;          // 0..191
    const int qt = blk & 31;          // 0..31
    const int tid = threadIdx.x;
    const int n0 = qt * 32;

    const float* Qg = g_q + (size_t)bh * HD * SEQ;
    const float* Kg = g_k + (size_t)bh * HD * SEQ;
    const float* Vg = g_v + (size_t)bh * SEQ * HD;

    // Load Q tile [64 dd][32 n], scaled by 1/sqrt(d)=0.125
    #pragma unroll
    for (int i = 0; i < 2; ++i) {
        int l = tid + i * 256;        // 0..511
        int dd = l >> 3, c = (l & 7) << 2;
        float4 v = *(const float4*)(Qg + (size_t)dd * SEQ + n0 + c);
        v.x *= 0.125f; v.y *= 0.125f; v.z *= 0.125f; v.w *= 0.125f;
        *(float4*)&Qs[dd * QS_STRIDE + c] = v;
    }

    // Phase 1: S = Q K^T over 8 key tiles of 128
    {
        const int tx = tid & 31, ty = tid >> 5;
        for (int kt = 0; kt < 8; ++kt) {
            __syncthreads();
            #pragma unroll
            for (int i = 0; i < 8; ++i) {
                int l = tid + i * 256;            // 0..2047
                int dd = l >> 5, c = (l & 31) << 2;
                float4 v = *(const float4*)(Kg + (size_t)dd * SEQ + kt * 128 + c);
                *(float4*)&Ks[dd * KS_STRIDE + c] = v;
            }
            __syncthreads();
            float acc[4][4];
            #pragma unroll
            for (int i = 0; i < 4; i++)
                #pragma unroll
                for (int j = 0; j < 4; j++) acc[i][j] = 0.f;
            #pragma unroll
            for (int dd = 0; dd < 64; ++dd) {
                float4 a = *(const float4*)&Qs[dd * QS_STRIDE + ty * 4];
                float4 b = *(const float4*)&Ks[dd * KS_STRIDE + tx * 4];
                float av[4] = {a.x, a.y, a.z, a.w};
                float bv2[4] = {b.x, b.y, b.z, b.w};
                #pragma unroll
                for (int i = 0; i < 4; i++)
                    #pragma unroll
                    for (int j = 0; j < 4; j++) acc[i][j] += av[i] * bv2[j];
            }
            #pragma unroll
            for (int i = 0; i < 4; i++)
                *(float4*)&Ss[(ty * 4 + i) * SS_STRIDE + kt * 128 + tx * 4] =
                    make_float4(acc[i][0], acc[i][1], acc[i][2], acc[i][3]);
        }
    }
    __syncthreads();

    // Phase 2: softmax over each 1024-wide row; 8 threads per row
    {
        const int r = tid >> 3, g = tid & 7;
        float* row = Ss + r * SS_STRIDE;
        float m = -1e30f;
        #pragma unroll 8
        for (int k = 0; k < 128; ++k) m = fmaxf(m, row[g + 8 * k]);
        m = fmaxf(m, __shfl_xor_sync(0xffffffffu, m, 4));
        m = fmaxf(m, __shfl_xor_sync(0xffffffffu, m, 2));
        m = fmaxf(m, __shfl_xor_sync(0xffffffffu, m, 1));
        float ssum = 0.f;
        #pragma unroll 8
        for (int k = 0; k < 128; ++k) {
            int idx = g + 8 * k;
            float e = __expf(row[idx] - m);
            row[idx] = e;
            ssum += e;
        }
        ssum += __shfl_xor_sync(0xffffffffu, ssum, 4);
        ssum += __shfl_xor_sync(0xffffffffu, ssum, 2);
        ssum += __shfl_xor_sync(0xffffffffu, ssum, 1);
        if (g == 0) rowsum[r] = ssum;
    }

    // Phase 3: O = P @ V. Warp w -> rows w*4..w*4+3; lane -> cols 2*lane,2*lane+1
    {
        const int w = tid >> 5, lane = tid & 31;
        const int r0 = w * 4;
        float o[4][2];
        #pragma unroll
        for (int i = 0; i < 4; i++) { o[i][0] = 0.f; o[i][1] = 0.f; }

        for (int kt = 0; kt < 8; ++kt) {
            __syncthreads();   // also guards Ss exp-writes & rowsum on first iter
            #pragma unroll
            for (int i = 0; i < 8; ++i) {
                int l = tid + i * 256;            // 0..2047
                int rowv = l >> 4, c = (l & 15) << 2;
                float4 v = *(const float4*)(Vg + (size_t)(kt * 128 + rowv) * HD + c);
                *(float4*)&Vs[rowv * VS_STRIDE + c] = v;
            }
            __syncthreads();
            #pragma unroll 4
            for (int j = 0; j < 128; j += 4) {
                float4 p[4];
                #pragma unroll
                for (int i = 0; i < 4; i++)
                    p[i] = *(const float4*)&Ss[(r0 + i) * SS_STRIDE + kt * 128 + j];
                #pragma unroll
                for (int jj = 0; jj < 4; jj++) {
                    float2 vv = *(const float2*)&Vs[(j + jj) * VS_STRIDE + (lane << 1)];
                    #pragma unroll
                    for (int i = 0; i < 4; i++) {
                        float pij = P_COMP(p[i], jj);
                        o[i][0] += pij * vv.x;
                        o[i][1] += pij * vv.y;
                    }
                }
            }
        }

        const int bb = bh / HEADS, h = bh % HEADS;
        #pragma unroll
        for (int i = 0; i < 4; i++) {
            int n = n0 + r0 + i;
            float inv = 1.0f / rowsum[r0 + i];
            float2 outv = make_float2(o[i][0] * inv, o[i][1] * inv);
            *(float2*)(g_att + ((size_t)(bb * SEQ + n)) * DIM + h * 64 + (lane << 1)) = outv;
        }
    }
}

// ---------------------------------------------------------------------------
// GEMM 2: out = g_att @ w_proj + b_proj
// ---------------------------------------------------------------------------
__global__ __launch_bounds__(256, 2)
void proj_gemm_kernel(const float* __restrict__ W,
                      const float* __restrict__ bias,
                      float* __restrict__ out) {
    __shared__ float As[16][132];
    __shared__ float Bs[16][132];

    const int K = DIM;   // 768
    const int NN = DIM;  // 768

    const int bn = blockIdx.x;           // 0..5
    const int bm = blockIdx.y;           // 0..127
    const int tid = threadIdx.x;
    const int tx = tid & 15;
    const int ty = tid >> 4;
    const int gm0 = bm * 128;
    const int gn0 = bn * 128;
    const float* X = g_att;

    float acc[8][8];
    #pragma unroll
    for (int i = 0; i < 8; i++)
        #pragma unroll
        for (int j = 0; j < 8; j++) acc[i][j] = 0.f;

    for (int kt = 0; kt < K / 16; ++kt) {
        #pragma unroll
        for (int i = 0; i < 2; ++i) {
            int l = tid + i * 256;
            int ar = l >> 2, ac = (l & 3) << 2;
            float4 va = *(const float4*)(X + (size_t)(gm0 + ar) * K + kt * 16 + ac);
            As[ac + 0][ar] = va.x;
            As[ac + 1][ar] = va.y;
            As[ac + 2][ar] = va.z;
            As[ac + 3][ar] = va.w;
            int br = l >> 5, bc = (l & 31) << 2;
            float4 vb = *(const float4*)(W + (size_t)(kt * 16 + br) * NN + gn0 + bc);
            *(float4*)&Bs[br][bc] = vb;
        }
        __syncthreads();
        #pragma unroll
        for (int kk = 0; kk < 16; ++kk) {
            float af[8], bf[8];
            *(float4*)(af + 0) = *(const float4*)&As[kk][ty * 8 + 0];
            *(float4*)(af + 4) = *(const float4*)&As[kk][ty * 8 + 4];
            *(float4*)(bf + 0) = *(const float4*)&Bs[kk][tx * 8 + 0];
            *(float4*)(bf + 4) = *(const float4*)&Bs[kk][tx * 8 + 4];
            #pragma unroll
            for (int i = 0; i < 8; i++)
                #pragma unroll
                for (int j = 0; j < 8; j++) acc[i][j] += af[i] * bf[j];
        }
        __syncthreads();
    }

    const int c0 = gn0 + tx * 8;
    const int m0 = gm0 + ty * 8;
    #pragma unroll
    for (int i = 0; i < 8; i++) {
        float* dst = out + (size_t)(m0 + i) * NN + c0;
        float4 lo = make_float4(acc[i][0] + bias[c0 + 0], acc[i][1] + bias[c0 + 1],
                                acc[i][2] + bias[c0 + 2], acc[i][3] + bias[c0 + 3]);
        float4 hi = make_float4(acc[i][4] + bias[c0 + 4], acc[i][5] + bias[c0 + 5],
                                acc[i][6] + bias[c0 + 6], acc[i][7] + bias[c0 + 7]);
        *(float4*)(dst + 0) = lo;
        *(float4*)(dst + 4) = hi;
    }
}

// ---------------------------------------------------------------------------
extern "C" void kernel_launch(void* const* d_in, const int* in_sizes, int n_in,
                              void* d_out, int out_size) {
    const float* x      = (const float*)d_in[0];
    const float* w_qkv  = (const float*)d_in[1];
    const float* b_qkv  = (const float*)d_in[2];
    const float* w_proj = (const float*)d_in[3];
    const float* b_proj = (const float*)d_in[4];
    float* out = (float*)d_out;

    (void)in_sizes; (void)n_in; (void)out_size;

    // opt-in to >48KB dynamic smem for the attention kernel (idempotent)
    cudaFuncSetAttribute(attn_kernel,
                         cudaFuncAttributeMaxDynamicSharedMemorySize,
                         ATTN_SMEM_BYTES);

    qkv_gemm_kernel<<<dim3(QKVN / 128, MTOT / 128), 256>>>(x, w_qkv, b_qkv);
    attn_kernel<<<NBH * (SEQ / 32), 256, ATTN_SMEM_BYTES>>>();
    proj_gemm_kernel<<<dim3(DIM / 128, MTOT / 128), 256>>>(w_proj, b_proj, out);
}

// round 5
// speedup vs baseline: 2.6886x; 2.6886x over previous
#include <cuda_runtime.h>
#include <math.h>
#include <stdint.h>

// ---------------------------------------------------------------------------
// MHSA via tf32 mma.sync tensor cores.
// All mma operands pre-rounded to tf32 (cvt.rna) exactly once, so products are
// exact and cp.async pipelines need no in-loop conversion.
// ---------------------------------------------------------------------------

#define BATCH   16
#define SEQ     1024
#define DIM     768
#define HEADS   12
#define HD      64
#define MTOT    (BATCH * SEQ)      // 16384
#define QKVN    (3 * DIM)          // 2304
#define NBH     (BATCH * HEADS)    // 192

// scratch (__device__ globals: no allocation anywhere)
__device__ float g_xr[(size_t)MTOT * DIM];        // rounded x
__device__ float g_wqr[(size_t)DIM * QKVN];       // rounded w_qkv
__device__ float g_wpr[(size_t)DIM * DIM];        // rounded w_proj
__device__ float g_q[(size_t)NBH * HD * SEQ];     // [bh][d][n], rounded
__device__ float g_k[(size_t)NBH * HD * SEQ];     // [bh][d][n], rounded
__device__ float g_v[(size_t)NBH * SEQ * HD];     // [bh][n][d], rounded
__device__ float g_att[(size_t)MTOT * DIM];       // [m][h*64+d], rounded

// ---------------------------------------------------------------------------
__device__ __forceinline__ uint32_t f2tf(float f) {
    uint32_t r;
    asm("cvt.rna.tf32.f32 %0, %1;" : "=r"(r) : "f"(f));
    return r;
}
__device__ __forceinline__ float roundtf(float f) {
    return __uint_as_float(f2tf(f));
}
__device__ __forceinline__ void mma8(float* c, const uint32_t* a, uint32_t b0, uint32_t b1) {
    asm volatile(
        "mma.sync.aligned.m16n8k8.row.col.f32.tf32.tf32.f32 "
        "{%0,%1,%2,%3}, {%4,%5,%6,%7}, {%8,%9}, {%0,%1,%2,%3};\n"
        : "+f"(c[0]), "+f"(c[1]), "+f"(c[2]), "+f"(c[3])
        : "r"(a[0]), "r"(a[1]), "r"(a[2]), "r"(a[3]), "r"(b0), "r"(b1));
}
__device__ __forceinline__ void cp16(void* dst_smem, const void* src) {
    uint32_t d = (uint32_t)__cvta_generic_to_shared(dst_smem);
    asm volatile("cp.async.cg.shared.global [%0], [%1], 16;" :: "r"(d), "l"(src));
}
#define CP_COMMIT() asm volatile("cp.async.commit_group;")
#define CP_WAIT0()  asm volatile("cp.async.wait_group 0;")
#define CP_WAIT1()  asm volatile("cp.async.wait_group 1;")

// ---------------------------------------------------------------------------
// Pre-pass: round fp32 arrays to tf32-representable fp32.
// ---------------------------------------------------------------------------
__device__ __forceinline__ float4 round4(float4 v) {
    v.x = roundtf(v.x); v.y = roundtf(v.y);
    v.z = roundtf(v.z); v.w = roundtf(v.w);
    return v;
}
__global__ void round_x_kernel(const float4* __restrict__ src) {
    int i = blockIdx.x * blockDim.x + threadIdx.x;
    if (i < MTOT * DIM / 4) ((float4*)g_xr)[i] = round4(src[i]);
}
__global__ void round_wq_kernel(const float4* __restrict__ src) {
    int i = blockIdx.x * blockDim.x + threadIdx.x;
    if (i < DIM * QKVN / 4) ((float4*)g_wqr)[i] = round4(src[i]);
}
__global__ void round_wp_kernel(const float4* __restrict__ src) {
    int i = blockIdx.x * blockDim.x + threadIdx.x;
    if (i < DIM * DIM / 4) ((float4*)g_wpr)[i] = round4(src[i]);
}

// ---------------------------------------------------------------------------
// QKV GEMM (M=16384, N=2304, K=768). 128x128 CTA, 8 warps of 64x32, mma tf32.
// Epilogue scatters rounded Q/K (d-major) and V (natural).
// ---------------------------------------------------------------------------
__global__ __launch_bounds__(256, 1)
void qkv_mma_kernel(const float* __restrict__ bias) {
    __shared__ float As[2][128][20];
    __shared__ float Bs[2][16][136];

    const float* X = g_xr;
    const float* W = g_wqr;

    const int tid = threadIdx.x;
    const int wid = tid >> 5, lane = tid & 31;
    const int g = lane >> 2, t = lane & 3;
    const int gm0 = blockIdx.y * 128, gn0 = blockIdx.x * 128;
    const int mbase = (wid >> 2) * 64, nbase = (wid & 3) * 32;

    float c[4][4][4];
    #pragma unroll
    for (int i = 0; i < 4; i++)
        #pragma unroll
        for (int j = 0; j < 4; j++)
            #pragma unroll
            for (int k = 0; k < 4; k++) c[i][j][k] = 0.f;

    auto loadA = [&](int b, int kt) {
        #pragma unroll
        for (int i = 0; i < 2; i++) {
            int l = tid + i * 256;
            int row = l >> 2, c4 = (l & 3) * 4;
            cp16(&As[b][row][c4], X + (size_t)(gm0 + row) * DIM + kt * 16 + c4);
        }
    };
    auto loadB = [&](int b, int kt) {
        #pragma unroll
        for (int i = 0; i < 2; i++) {
            int l = tid + i * 256;
            int row = l >> 5, c4 = (l & 31) * 4;
            cp16(&Bs[b][row][c4], W + (size_t)(kt * 16 + row) * QKVN + gn0 + c4);
        }
    };

    loadA(0, 0); loadB(0, 0); CP_COMMIT();
    int buf = 0;
    for (int kt = 0; kt < 48; ++kt) {
        if (kt < 47) {
            loadA(buf ^ 1, kt + 1); loadB(buf ^ 1, kt + 1); CP_COMMIT();
            CP_WAIT1();
        } else {
            CP_WAIT0();
        }
        __syncthreads();
        #pragma unroll
        for (int ks = 0; ks < 2; ++ks) {
            const int k0 = ks * 8;
            uint32_t a[4][4];
            #pragma unroll
            for (int mt = 0; mt < 4; ++mt) {
                int r0 = mbase + mt * 16 + g;
                a[mt][0] = __float_as_uint(As[buf][r0][k0 + t]);
                a[mt][1] = __float_as_uint(As[buf][r0 + 8][k0 + t]);
                a[mt][2] = __float_as_uint(As[buf][r0][k0 + t + 4]);
                a[mt][3] = __float_as_uint(As[buf][r0 + 8][k0 + t + 4]);
            }
            #pragma unroll
            for (int nt = 0; nt < 4; ++nt) {
                uint32_t b0 = __float_as_uint(Bs[buf][k0 + t][nbase + nt * 8 + g]);
                uint32_t b1 = __float_as_uint(Bs[buf][k0 + t + 4][nbase + nt * 8 + g]);
                #pragma unroll
                for (int mt = 0; mt < 4; ++mt) mma8(c[mt][nt], a[mt], b0, b1);
            }
        }
        __syncthreads();
        buf ^= 1;
    }

    // epilogue: scatter with bias, rounded to tf32
    int   sv[4][2], hv[4][2], ddv[4][2];
    float bv[4][2];
    #pragma unroll
    for (int nt = 0; nt < 4; ++nt)
        #pragma unroll
        for (int cc = 0; cc < 2; ++cc) {
            int col = gn0 + nbase + nt * 8 + 2 * t + cc;
            bv[nt][cc] = bias[col];
            int s = col / 768, rm = col - s * 768;
            sv[nt][cc] = s; hv[nt][cc] = rm >> 6; ddv[nt][cc] = rm & 63;
        }
    #pragma unroll
    for (int mt = 0; mt < 4; ++mt)
        #pragma unroll
        for (int i2 = 0; i2 < 2; ++i2) {
            int m = gm0 + mbase + mt * 16 + g + i2 * 8;
            int bb = m >> 10, n = m & 1023;
            #pragma unroll
            for (int nt = 0; nt < 4; ++nt)
                #pragma unroll
                for (int cc = 0; cc < 2; ++cc) {
                    float v = roundtf(c[mt][nt][i2 * 2 + cc] + bv[nt][cc]);
                    int s = sv[nt][cc], h = hv[nt][cc], dd = ddv[nt][cc];
                    int bh = bb * HEADS + h;
                    if (s == 2)
                        g_v[((size_t)bh * SEQ + n) * HD + dd] = v;
                    else if (s == 1)
                        g_k[((size_t)bh * HD + dd) * SEQ + n] = v;
                    else
                        g_q[((size_t)bh * HD + dd) * SEQ + n] = v;
                }
        }
}

// ---------------------------------------------------------------------------
// Attention: CTA = (bh, 32 q-rows). Full S row in smem, exact softmax,
// O^T = V^T P^T with warp k-split + reduction.
// ---------------------------------------------------------------------------
#define SS_FLOATS (32 * 1032)
#define KV_FLOATS (2 * 128 * 72)          // 18432 (>= 2*64*136 for K bufs)
#define QS_FLOATS (64 * 40)
#define ATT_SMEM_BYTES ((SS_FLOATS + KV_FLOATS + QS_FLOATS + 32) * 4)

__global__ __launch_bounds__(256, 1)
void attn_mma_kernel() {
    extern __shared__ float sm[];
    float* Ss = sm;                        // [32][1032] scores / P / Ored
    float* KV = sm + SS_FLOATS;            // K: [2][64][136] | V: [2][128][72]
    float* Qs = KV + KV_FLOATS;            // [64][40]
    float* rsum = Qs + QS_FLOATS;          // [32] inverse rowsums

    const int blk = blockIdx.x;
    const int bh = blk >> 5, qt = blk & 31;
    const int bb = bh / HEADS, h = bh - bb * HEADS;
    const int n0 = qt * 32;
    const int tid = threadIdx.x;
    const int w = tid >> 5, lane = tid & 31;
    const int g = lane >> 2, t = lane & 3;

    const float* Qg = g_q + (size_t)bh * HD * SEQ;
    const float* Kg = g_k + (size_t)bh * HD * SEQ;
    const float* Vg = g_v + (size_t)bh * SEQ * HD;

    auto issueK = [&](int b, int kt) {
        #pragma unroll
        for (int i = 0; i < 8; i++) {
            int l = tid + i * 256;
            int d = l >> 5, c4 = (l & 31) * 4;
            cp16(&KV[b * 8704 + d * 136 + c4], Kg + (size_t)d * SEQ + kt * 128 + c4);
        }
    };
    auto issueV = [&](int b, int kt) {
        #pragma unroll
        for (int i = 0; i < 8; i++) {
            int l = tid + i * 256;
            int j = l >> 4, c4 = (l & 15) * 4;
            cp16(&KV[b * 9216 + j * 72 + c4], Vg + (size_t)(kt * 128 + j) * HD + c4);
        }
    };

    // start K tile 0 fetch immediately
    issueK(0, 0); CP_COMMIT();

    // load Q tile [64 d][32 n] scaled by 0.125 (exact power of 2 -> stays tf32)
    #pragma unroll
    for (int i = 0; i < 2; i++) {
        int l = tid + i * 256;
        int d = l >> 3, c4 = (l & 7) * 4;
        float4 v = *(const float4*)(Qg + (size_t)d * SEQ + n0 + c4);
        v.x *= 0.125f; v.y *= 0.125f; v.z *= 0.125f; v.w *= 0.125f;
        *(float4*)&Qs[d * 40 + c4] = v;
    }
    __syncthreads();

    // preload Q fragments: 2 m-tiles x 8 ksteps
    uint32_t aq[2][8][4];
    #pragma unroll
    for (int mt = 0; mt < 2; ++mt)
        #pragma unroll
        for (int ks = 0; ks < 8; ++ks) {
            aq[mt][ks][0] = __float_as_uint(Qs[(ks * 8 + t) * 40 + mt * 16 + g]);
            aq[mt][ks][1] = __float_as_uint(Qs[(ks * 8 + t) * 40 + mt * 16 + g + 8]);
            aq[mt][ks][2] = __float_as_uint(Qs[(ks * 8 + t + 4) * 40 + mt * 16 + g]);
            aq[mt][ks][3] = __float_as_uint(Qs[(ks * 8 + t + 4) * 40 + mt * 16 + g + 8]);
        }

    // Phase 1: S = (Q*scale) K^T, warp w handles keys [w*16, w*16+16) per tile
    int kb = 0;
    for (int kt = 0; kt < 8; ++kt) {
        if (kt < 7) { issueK(kb ^ 1, kt + 1); CP_COMMIT(); CP_WAIT1(); }
        else        { CP_WAIT0(); }
        __syncthreads();

        float cS[2][2][4];
        #pragma unroll
        for (int mt = 0; mt < 2; mt++)
            #pragma unroll
            for (int nt = 0; nt < 2; nt++)
                #pragma unroll
                for (int k = 0; k < 4; k++) cS[mt][nt][k] = 0.f;

        #pragma unroll
        for (int ks = 0; ks < 8; ++ks) {
            #pragma unroll
            for (int nt = 0; nt < 2; ++nt) {
                uint32_t b0 = __float_as_uint(KV[kb * 8704 + (ks * 8 + t) * 136 + w * 16 + nt * 8 + g]);
                uint32_t b1 = __float_as_uint(KV[kb * 8704 + (ks * 8 + t + 4) * 136 + w * 16 + nt * 8 + g]);
                #pragma unroll
                for (int mt = 0; mt < 2; ++mt) mma8(cS[mt][nt], aq[mt][ks], b0, b1);
            }
        }
        #pragma unroll
        for (int mt = 0; mt < 2; ++mt)
            #pragma unroll
            for (int nt = 0; nt < 2; ++nt) {
                int q = mt * 16 + g;
                int col = kt * 128 + w * 16 + nt * 8 + 2 * t;
                *(float2*)&Ss[q * 1032 + col] = make_float2(cS[mt][nt][0], cS[mt][nt][1]);
                *(float2*)&Ss[(q + 8) * 1032 + col] = make_float2(cS[mt][nt][2], cS[mt][nt][3]);
            }
        __syncthreads();
        kb ^= 1;
    }

    // Phase 2: exact softmax, write rounded exp values
    {
        const int r = tid >> 3, gg = tid & 7;
        float* row = Ss + r * 1032;
        float m = -1e30f;
        #pragma unroll 8
        for (int k = 0; k < 128; ++k) m = fmaxf(m, row[gg + 8 * k]);
        m = fmaxf(m, __shfl_xor_sync(0xffffffffu, m, 4));
        m = fmaxf(m, __shfl_xor_sync(0xffffffffu, m, 2));
        m = fmaxf(m, __shfl_xor_sync(0xffffffffu, m, 1));
        float ssum = 0.f;
        #pragma unroll 8
        for (int k = 0; k < 128; ++k) {
            int idx = gg + 8 * k;
            float e = __expf(row[idx] - m);
            row[idx] = roundtf(e);
            ssum += e;
        }
        ssum += __shfl_xor_sync(0xffffffffu, ssum, 4);
        ssum += __shfl_xor_sync(0xffffffffu, ssum, 2);
        ssum += __shfl_xor_sync(0xffffffffu, ssum, 1);
        if (gg == 0) rsum[r] = 1.0f / ssum;
    }
    __syncthreads();

    // Phase 3: O^T = V^T P^T.  Warp w covers full 64x32 O^T, k-slice = 16 j per tile.
    float cO[4][4][4];
    #pragma unroll
    for (int i = 0; i < 4; i++)
        #pragma unroll
        for (int j = 0; j < 4; j++)
            #pragma unroll
            for (int k = 0; k < 4; k++) cO[i][j][k] = 0.f;

    issueV(0, 0); CP_COMMIT();
    int vb = 0;
    for (int kt = 0; kt < 8; ++kt) {
        if (kt < 7) { issueV(vb ^ 1, kt + 1); CP_COMMIT(); CP_WAIT1(); }
        else        { CP_WAIT0(); }
        __syncthreads();
        #pragma unroll
        for (int ks = 0; ks < 2; ++ks) {
            const int j0 = w * 16 + ks * 8;
            uint32_t av[4][4];
            #pragma unroll
            for (int mt = 0; mt < 4; ++mt) {
                av[mt][0] = __float_as_uint(KV[vb * 9216 + (j0 + t) * 72 + mt * 16 + g]);
                av[mt][1] = __float_as_uint(KV[vb * 9216 + (j0 + t) * 72 + mt * 16 + g + 8]);
                av[mt][2] = __float_as_uint(KV[vb * 9216 + (j0 + t + 4) * 72 + mt * 16 + g]);
                av[mt][3] = __float_as_uint(KV[vb * 9216 + (j0 + t + 4) * 72 + mt * 16 + g + 8]);
            }
            #pragma unroll
            for (int nt = 0; nt < 4; ++nt) {
                int q = nt * 8 + g;
                uint32_t b0 = __float_as_uint(Ss[q * 1032 + kt * 128 + j0 + t]);
                uint32_t b1 = __float_as_uint(Ss[q * 1032 + kt * 128 + j0 + t + 4]);
                #pragma unroll
                for (int mt = 0; mt < 4; ++mt) mma8(cO[mt][nt], av[mt], b0, b1);
            }
        }
        __syncthreads();
        vb ^= 1;
    }

    // store partials (reuse Ss region) and reduce across warps
    float* Ored = Ss;   // [8][64][34]
    #pragma unroll
    for (int mt = 0; mt < 4; ++mt)
        #pragma unroll
        for (int nt = 0; nt < 4; ++nt) {
            int dd = mt * 16 + g;
            int q2 = nt * 8 + 2 * t;
            int base = w * 2176;
            *(float2*)&Ored[base + dd * 34 + q2] = make_float2(cO[mt][nt][0], cO[mt][nt][1]);
            *(float2*)&Ored[base + (dd + 8) * 34 + q2] = make_float2(cO[mt][nt][2], cO[mt][nt][3]);
        }
    __syncthreads();

    {
        const int q = tid >> 3, dd0 = (tid & 7) * 8;
        const float inv = rsum[q];
        float o[8];
        #pragma unroll
        for (int jj = 0; jj < 8; ++jj) {
            float s = 0.f;
            #pragma unroll
            for (int w2 = 0; w2 < 8; ++w2)
                s += Ored[w2 * 2176 + (dd0 + jj) * 34 + q];
            o[jj] = roundtf(s * inv);
        }
        float* dst = g_att + ((size_t)(bb * SEQ + n0 + q)) * DIM + h * 64 + dd0;
        *(float4*)(dst + 0) = make_float4(o[0], o[1], o[2], o[3]);
        *(float4*)(dst + 4) = make_float4(o[4], o[5], o[6], o[7]);
    }
}

// ---------------------------------------------------------------------------
// Proj GEMM (M=16384, N=768, K=768), same mainloop, fp32 output.
// ---------------------------------------------------------------------------
__global__ __launch_bounds__(256, 1)
void proj_mma_kernel(const float* __restrict__ bias,
                     float* __restrict__ out) {
    __shared__ float As[2][128][20];
    __shared__ float Bs[2][16][136];

    const int tid = threadIdx.x;
    const int wid = tid >> 5, lane = tid & 31;
    const int g = lane >> 2, t = lane & 3;
    const int gm0 = blockIdx.y * 128, gn0 = blockIdx.x * 128;
    const int mbase = (wid >> 2) * 64, nbase = (wid & 3) * 32;
    const float* X = g_att;
    const float* W = g_wpr;

    float c[4][4][4];
    #pragma unroll
    for (int i = 0; i < 4; i++)
        #pragma unroll
        for (int j = 0; j < 4; j++)
            #pragma unroll
            for (int k = 0; k < 4; k++) c[i][j][k] = 0.f;

    auto loadA = [&](int b, int kt) {
        #pragma unroll
        for (int i = 0; i < 2; i++) {
            int l = tid + i * 256;
            int row = l >> 2, c4 = (l & 3) * 4;
            cp16(&As[b][row][c4], X + (size_t)(gm0 + row) * DIM + kt * 16 + c4);
        }
    };
    auto loadB = [&](int b, int kt) {
        #pragma unroll
        for (int i = 0; i < 2; i++) {
            int l = tid + i * 256;
            int row = l >> 5, c4 = (l & 31) * 4;
            cp16(&Bs[b][row][c4], W + (size_t)(kt * 16 + row) * DIM + gn0 + c4);
        }
    };

    loadA(0, 0); loadB(0, 0); CP_COMMIT();
    int buf = 0;
    for (int kt = 0; kt < 48; ++kt) {
        if (kt < 47) {
            loadA(buf ^ 1, kt + 1); loadB(buf ^ 1, kt + 1); CP_COMMIT();
            CP_WAIT1();
        } else {
            CP_WAIT0();
        }
        __syncthreads();
        #pragma unroll
        for (int ks = 0; ks < 2; ++ks) {
            const int k0 = ks * 8;
            uint32_t a[4][4];
            #pragma unroll
            for (int mt = 0; mt < 4; ++mt) {
                int r0 = mbase + mt * 16 + g;
                a[mt][0] = __float_as_uint(As[buf][r0][k0 + t]);
                a[mt][1] = __float_as_uint(As[buf][r0 + 8][k0 + t]);
                a[mt][2] = __float_as_uint(As[buf][r0][k0 + t + 4]);
                a[mt][3] = __float_as_uint(As[buf][r0 + 8][k0 + t + 4]);
            }
            #pragma unroll
            for (int nt = 0; nt < 4; ++nt) {
                uint32_t b0 = __float_as_uint(Bs[buf][k0 + t][nbase + nt * 8 + g]);
                uint32_t b1 = __float_as_uint(Bs[buf][k0 + t + 4][nbase + nt * 8 + g]);
                #pragma unroll
                for (int mt = 0; mt < 4; ++mt) mma8(c[mt][nt], a[mt], b0, b1);
            }
        }
        __syncthreads();
        buf ^= 1;
    }

    #pragma unroll
    for (int mt = 0; mt < 4; ++mt)
        #pragma unroll
        for (int i2 = 0; i2 < 2; ++i2) {
            int m = gm0 + mbase + mt * 16 + g + i2 * 8;
            #pragma unroll
            for (int nt = 0; nt < 4; ++nt) {
                int col = gn0 + nbase + nt * 8 + 2 * t;
                float2 ov = make_float2(c[mt][nt][i2 * 2 + 0] + bias[col],
                                        c[mt][nt][i2 * 2 + 1] + bias[col + 1]);
                *(float2*)(out + (size_t)m * DIM + col) = ov;
            }
        }
}

// ---------------------------------------------------------------------------
extern "C" void kernel_launch(void* const* d_in, const int* in_sizes, int n_in,
                              void* d_out, int out_size) {
    const float* x      = (const float*)d_in[0];
    const float* w_qkv  = (const float*)d_in[1];
    const float* b_qkv  = (const float*)d_in[2];
    const float* w_proj = (const float*)d_in[3];
    const float* b_proj = (const float*)d_in[4];
    float* out = (float*)d_out;
    (void)in_sizes; (void)n_in; (void)out_size;

    cudaFuncSetAttribute(attn_mma_kernel,
                         cudaFuncAttributeMaxDynamicSharedMemorySize,
                         ATT_SMEM_BYTES);

    round_x_kernel<<<(MTOT * DIM / 4 + 255) / 256, 256>>>((const float4*)x);
    round_wq_kernel<<<(DIM * QKVN / 4 + 255) / 256, 256>>>((const float4*)w_qkv);
    round_wp_kernel<<<(DIM * DIM / 4 + 255) / 256, 256>>>((const float4*)w_proj);

    qkv_mma_kernel<<<dim3(QKVN / 128, MTOT / 128), 256>>>(b_qkv);
    attn_mma_kernel<<<NBH * (SEQ / 32), 256, ATT_SMEM_BYTES>>>();
    proj_mma_kernel<<<dim3(DIM / 128, MTOT / 128), 256>>>(b_proj, out);
}